// round 15
// baseline (speedup 1.0000x reference)
#include <cuda_runtime.h>
#include <cuda_bf16.h>
#include <cstdint>

#define B_  4
#define N_  1024
#define D_  1024
#define H_  16
#define HD_ 64
#define M_  (B_*N_)   // 4096 token rows

// Scratch (device globals — no runtime allocation allowed)
__device__ __nv_bfloat16 g_xn  [M_ * D_];        // LN output (bf16 GEMM A)
__device__ __nv_bfloat16 g_qkv [M_ * 3 * D_];    // QKV output (bf16)
__device__ __nv_bfloat16 g_att [M_ * D_];        // attention output (bf16)
__device__ __nv_bfloat16 g_wqkv[D_ * 3 * D_];    // w_qkv bf16
__device__ __nv_bfloat16 g_wprj[D_ * D_];        // w_proj bf16

// ---------------------------------------------------------------------------
// Helpers
// ---------------------------------------------------------------------------
__device__ __forceinline__ void mma_bf16(float* c, const uint32_t* a, const uint32_t* b) {
    asm volatile(
        "mma.sync.aligned.m16n8k16.row.col.f32.bf16.bf16.f32 "
        "{%0,%1,%2,%3}, {%4,%5,%6,%7}, {%8,%9}, {%0,%1,%2,%3};\n"
        : "+f"(c[0]), "+f"(c[1]), "+f"(c[2]), "+f"(c[3])
        : "r"(a[0]), "r"(a[1]), "r"(a[2]), "r"(a[3]), "r"(b[0]), "r"(b[1]));
}
__device__ __forceinline__ void ldsm4(uint32_t* r, uint32_t saddr) {
    asm volatile("ldmatrix.sync.aligned.m8n8.x4.shared.b16 {%0,%1,%2,%3}, [%4];\n"
        : "=r"(r[0]), "=r"(r[1]), "=r"(r[2]), "=r"(r[3]) : "r"(saddr));
}
__device__ __forceinline__ void ldsm4t(uint32_t* r, uint32_t saddr) {
    asm volatile("ldmatrix.sync.aligned.m8n8.x4.trans.shared.b16 {%0,%1,%2,%3}, [%4];\n"
        : "=r"(r[0]), "=r"(r[1]), "=r"(r[2]), "=r"(r[3]) : "r"(saddr));
}
__device__ __forceinline__ void cp16(void* smem_dst, const void* gmem_src) {
    const uint32_t s = (uint32_t)__cvta_generic_to_shared(smem_dst);
    asm volatile("cp.async.cg.shared.global [%0], [%1], 16;\n" :: "r"(s), "l"(gmem_src));
}
#define CP_COMMIT() asm volatile("cp.async.commit_group;\n" ::: "memory")
#define CP_WAIT(n)  asm volatile("cp.async.wait_group %0;\n" :: "n"(n) : "memory")

__device__ __forceinline__ uint32_t pack_bf2(float a, float b) {
    __nv_bfloat162 h = __float22bfloat162_rn(make_float2(a, b));
    return *reinterpret_cast<uint32_t*>(&h);
}

// ---------------------------------------------------------------------------
// fp32 -> bf16 weight conversion (grid-stride over float4)
// ---------------------------------------------------------------------------
__global__ __launch_bounds__(256) void cvt_kernel(
    const float* __restrict__ src, __nv_bfloat16* __restrict__ dst, int n4)
{
    const int i = blockIdx.x * blockDim.x + threadIdx.x;
    if (i < n4) {
        const float4 v = reinterpret_cast<const float4*>(src)[i];
        uint2 u;
        u.x = pack_bf2(v.x, v.y);
        u.y = pack_bf2(v.z, v.w);
        reinterpret_cast<uint2*>(dst)[i] = u;
    }
}

// ---------------------------------------------------------------------------
// LayerNorm: ONE WARP per row (no barriers, no smem). 8 warps/block.
// Each lane holds 8 float4 = 32 values; shuffle-only reductions.
// ---------------------------------------------------------------------------
__global__ __launch_bounds__(256) void ln_kernel(
    const float* __restrict__ x, const float* __restrict__ gamma,
    const float* __restrict__ beta, __nv_bfloat16* __restrict__ out)
{
    const int warp = threadIdx.x >> 5, lane = threadIdx.x & 31;
    const int row = blockIdx.x * 8 + warp;
    const float4* xr = reinterpret_cast<const float4*>(x) + (size_t)row * 256;

    float4 v[8];
    float s = 0.f;
#pragma unroll
    for (int i = 0; i < 8; i++) {
        v[i] = xr[lane + i * 32];
        s += v[i].x + v[i].y + v[i].z + v[i].w;
    }
#pragma unroll
    for (int o = 16; o > 0; o >>= 1) s += __shfl_xor_sync(0xffffffffu, s, o);
    const float mean = s * (1.0f / D_);

    float sq = 0.f;
#pragma unroll
    for (int i = 0; i < 8; i++) {
        v[i].x -= mean; v[i].y -= mean; v[i].z -= mean; v[i].w -= mean;
        sq += v[i].x * v[i].x + v[i].y * v[i].y + v[i].z * v[i].z + v[i].w * v[i].w;
    }
#pragma unroll
    for (int o = 16; o > 0; o >>= 1) sq += __shfl_xor_sync(0xffffffffu, sq, o);
    const float rstd = rsqrtf(sq * (1.0f / D_) + 1e-5f);

    uint2* orow = reinterpret_cast<uint2*>(out) + (size_t)row * 256;
#pragma unroll
    for (int i = 0; i < 8; i++) {
        const float4 g = reinterpret_cast<const float4*>(gamma)[lane + i * 32];
        const float4 b = reinterpret_cast<const float4*>(beta)[lane + i * 32];
        uint2 u;
        u.x = pack_bf2(v[i].x * rstd * g.x + b.x, v[i].y * rstd * g.y + b.y);
        u.y = pack_bf2(v[i].z * rstd * g.z + b.z, v[i].w * rstd * g.w + b.w);
        orow[lane + i * 32] = u;
    }
}

// ---------------------------------------------------------------------------
// BF16 tensor-core GEMM, 3-stage cp.async pipeline, K-step 32, ONE barrier/iter.
// C[M_, NC] = A[M_, 1024] @ W[1024, NC], A/W bf16.
// 128x128 block tile, 8 warps (2x4), warp tile 64x32.
// Pipeline: prologue issues stages 0,1; iter t: wait(<=1 pending), sync,
// issue(t+2) into stage (t+2)%3 (reader of that stage, compute(t-1), is done
// by the barrier), compute(t). Tail: wait(0) at t=31.
// ---------------------------------------------------------------------------
#define GA_PITCH 40
#define GB_PITCH 136
#define GA_STG_BYTES (128 * GA_PITCH * 2)   // 10240
#define GB_STG_BYTES (32 * GB_PITCH * 2)    // 8704
#define GEMM_SMEM_BYTES (3 * (GA_STG_BYTES + GB_STG_BYTES))   // 56832

template <int NC, bool PROJ>
__global__ __launch_bounds__(256) void bf16_gemm_kernel(
    const __nv_bfloat16* __restrict__ A, const __nv_bfloat16* __restrict__ W,
    void* __restrict__ Cv, const float* __restrict__ bias,
    const float* __restrict__ resid)
{
    extern __shared__ char smc[];
    __nv_bfloat16* Asm = (__nv_bfloat16*)smc;                        // 3 stages
    __nv_bfloat16* Bsm = (__nv_bfloat16*)(smc + 3 * GA_STG_BYTES);   // 3 stages

    const int tid  = threadIdx.x;
    const int lane = tid & 31;
    const int warp = tid >> 5;
    const int wm = (warp >> 2) * 64;
    const int wn = (warp & 3) * 32;
    const int l4 = lane & 3, l8 = lane >> 2;

    const int rb = blockIdx.y * 128;
    const int cb = blockIdx.x * 128;

    const uint32_t as_b = (uint32_t)__cvta_generic_to_shared(Asm);
    const uint32_t bs_b = (uint32_t)__cvta_generic_to_shared(Bsm);
    uint32_t a_addr[4];
#pragma unroll
    for (int mi = 0; mi < 4; mi++)
        a_addr[mi] = as_b + ((wm + mi * 16 + (lane & 15)) * GA_PITCH
                             + ((lane >> 4) & 1) * 8) * 2;
    const uint32_t b_addr = bs_b
        + ((((lane & 7) + ((lane >> 3) & 1) * 8)) * GB_PITCH
           + ((lane >> 4) & 1) * 8 + wn) * 2;

    float c[4][4][4];
#pragma unroll
    for (int mi = 0; mi < 4; mi++)
#pragma unroll
        for (int ni = 0; ni < 4; ni++)
#pragma unroll
            for (int j = 0; j < 4; j++) c[mi][ni][j] = 0.f;

    auto issue_tile = [&](int k0, int st) {
        __nv_bfloat16* sA = Asm + st * (GA_STG_BYTES / 2);
        __nv_bfloat16* sB = Bsm + st * (GB_STG_BYTES / 2);
#pragma unroll
        for (int i = 0; i < 2; i++) {
            const int f = tid + i * 256;          // 512 16B chunks each
            cp16(&sA[(f >> 2) * GA_PITCH + (f & 3) * 8],
                 A + (size_t)(rb + (f >> 2)) * D_ + k0 + (f & 3) * 8);
            cp16(&sB[(f >> 4) * GB_PITCH + (f & 15) * 8],
                 W + (size_t)(k0 + (f >> 4)) * NC + cb + (f & 15) * 8);
        }
        CP_COMMIT();
    };

    issue_tile(0, 0);
    issue_tile(32, 1);

    int st = 0;
    for (int it = 0; it < 32; ++it) {
        if (it < 31) { CP_WAIT(1); } else { CP_WAIT(0); }
        __syncthreads();
        if (it < 30) {
            int isg = st + 2; if (isg >= 3) isg -= 3;
            issue_tile((it + 2) * 32, isg);
        }

        const uint32_t ao = (uint32_t)st * GA_STG_BYTES;
        const uint32_t bo = (uint32_t)st * GB_STG_BYTES;
#pragma unroll
        for (int ks = 0; ks < 32; ks += 16) {
            uint32_t a[4][4], bb[2][4];
#pragma unroll
            for (int mi = 0; mi < 4; mi++)
                ldsm4(a[mi], a_addr[mi] + ao + ks * 2);
#pragma unroll
            for (int np = 0; np < 2; np++)
                ldsm4t(bb[np], b_addr + bo + ks * (GB_PITCH * 2) + np * 32);
#pragma unroll
            for (int mi = 0; mi < 4; mi++)
#pragma unroll
                for (int np = 0; np < 2; np++) {
                    mma_bf16(c[mi][2 * np],     a[mi], bb[np]);
                    mma_bf16(c[mi][2 * np + 1], a[mi], bb[np] + 2);
                }
        }
        if (++st == 3) st = 0;
    }

#pragma unroll
    for (int mi = 0; mi < 4; mi++) {
        const int r0 = rb + wm + mi * 16 + l8;
#pragma unroll
        for (int ni = 0; ni < 4; ni++) {
            const int col = cb + wn + ni * 8 + l4 * 2;
            if (PROJ) {
                float* C = (float*)Cv;
                float2 v0 = {c[mi][ni][0], c[mi][ni][1]};
                float2 v1 = {c[mi][ni][2], c[mi][ni][3]};
                const float2 bz = *reinterpret_cast<const float2*>(bias + col);
                const float2 r0x = *reinterpret_cast<const float2*>(resid + (size_t)r0 * D_ + col);
                const float2 r1x = *reinterpret_cast<const float2*>(resid + (size_t)(r0 + 8) * D_ + col);
                v0.x += bz.x + r0x.x; v0.y += bz.y + r0x.y;
                v1.x += bz.x + r1x.x; v1.y += bz.y + r1x.y;
                *reinterpret_cast<float2*>(C + (size_t)r0 * NC + col) = v0;
                *reinterpret_cast<float2*>(C + (size_t)(r0 + 8) * NC + col) = v1;
            } else {
                __nv_bfloat16* C = (__nv_bfloat16*)Cv;
                *reinterpret_cast<uint32_t*>(C + (size_t)r0 * NC + col)
                    = pack_bf2(c[mi][ni][0], c[mi][ni][1]);
                *reinterpret_cast<uint32_t*>(C + (size_t)(r0 + 8) * NC + col)
                    = pack_bf2(c[mi][ni][2], c[mi][ni][3]);
            }
        }
    }
}

// ---------------------------------------------------------------------------
// BF16 mma flash attention (R13 winner, unchanged): occ 2, register-resident P.
// ---------------------------------------------------------------------------
#define AQ_BYTE 0
#define AK_BYTE 18432
#define AK_STG  18432
#define AV_BYTE 55296
#define ATT_SMEM_BYTES 73728

__global__ __launch_bounds__(256, 2) void attn_bf16_kernel(
    const __nv_bfloat16* __restrict__ qkv, const float* __restrict__ sim,
    const float* __restrict__ swlp, __nv_bfloat16* __restrict__ att)
{
    extern __shared__ char smc[];
    __nv_bfloat16* Qs = (__nv_bfloat16*)(smc + AQ_BYTE);
    __nv_bfloat16* Ks = (__nv_bfloat16*)(smc + AK_BYTE);
    __nv_bfloat16* Vs = (__nv_bfloat16*)(smc + AV_BYTE);

    const int tid  = threadIdx.x;
    const int lane = tid & 31, warp = tid >> 5;
    const int l4 = lane & 3, l8 = lane >> 2;
    const int wm = warp * 16;
    const int qb = blockIdx.x * 128;
    const int b  = blockIdx.y >> 4, h = blockIdx.y & 15;

    const float alpha = 1.f / (1.f + __expf(-(*swlp)));
    const float c1 = (1.f - alpha) * 0.125f;
    const float c2 = alpha;

    const __nv_bfloat16* qp    = qkv + (size_t)(b * N_ + qb) * 3 * D_ + h * HD_;
    const __nv_bfloat16* kbase = qkv + (size_t)(b * N_) * 3 * D_ + D_ + h * HD_;
    const __nv_bfloat16* vbase = qkv + (size_t)(b * N_) * 3 * D_ + 2 * D_ + h * HD_;

    const uint32_t smb = (uint32_t)__cvta_generic_to_shared(smc);
    const uint32_t q_ld = smb + AQ_BYTE
        + ((wm + (lane & 15)) * 72 + ((lane >> 4) & 1) * 8) * 2;
    const uint32_t k_ln = smb + AK_BYTE
        + ((((lane >> 4) & 1) * 8 + (lane & 7)) * 72 + ((lane >> 3) & 1) * 8) * 2;
    const uint32_t v_ln = smb + AV_BYTE
        + (((lane & 7) + ((lane >> 3) & 1) * 8) * 72 + ((lane >> 4) & 1) * 8) * 2;

#pragma unroll
    for (int i = 0; i < 4; i++) {
        const int idx = tid + i * 256;
        const int r = idx >> 3, c8 = (idx & 7) * 8;
        cp16(&Qs[r * 72 + c8], qp + (size_t)r * 3 * D_ + c8);
        cp16(&Ks[r * 72 + c8], kbase + (size_t)r * 3 * D_ + c8);
    }
    CP_COMMIT();

    float o[8][4];
#pragma unroll
    for (int ni = 0; ni < 8; ni++)
#pragma unroll
        for (int j = 0; j < 4; j++) o[ni][j] = 0.f;
    float m0 = -1e30f, m1 = -1e30f, l0 = 0.f, l1 = 0.f;

    for (int t = 0; t < 8; t++) {
        const int kb = t * 128;
        const uint32_t kst = k_ln + (t & 1) * AK_STG;

        __syncthreads();

#pragma unroll
        for (int i = 0; i < 4; i++) {
            const int idx = tid + i * 256;
            const int r = idx >> 3, c8 = (idx & 7) * 8;
            cp16(&Vs[r * 72 + c8], vbase + (size_t)(kb + r) * 3 * D_ + c8);
        }
        CP_COMMIT();

        CP_WAIT(1);
        __syncthreads();

        float s[16][4];
#pragma unroll
        for (int ni = 0; ni < 16; ni++)
#pragma unroll
            for (int j = 0; j < 4; j++) s[ni][j] = 0.f;
#pragma unroll
        for (int ks = 0; ks < 64; ks += 16) {
            uint32_t a[4];
            ldsm4(a, q_ld + ks * 2);
#pragma unroll
            for (int j = 0; j < 8; j++) {
                uint32_t bb[4];
                ldsm4(bb, kst + j * 2304 + ks * 2);
                mma_bf16(s[2 * j],     a, bb);
                mma_bf16(s[2 * j + 1], a, bb + 2);
            }
        }

        if (t < 7) {
            __nv_bfloat16* Kn = Ks + ((t + 1) & 1) * (AK_STG / 2);
#pragma unroll
            for (int i = 0; i < 4; i++) {
                const int idx = tid + i * 256;
                const int r = idx >> 3, c8 = (idx & 7) * 8;
                cp16(&Kn[r * 72 + c8], kbase + (size_t)(kb + 128 + r) * 3 * D_ + c8);
            }
            CP_COMMIT();
            CP_WAIT(1);
        } else {
            CP_WAIT(0);
        }
        __syncthreads();

        const float* simp = sim + (size_t)(qb + wm + l8) * N_ + kb;
        float zx0 = -1e30f, zx1 = -1e30f;
#pragma unroll
        for (int ni = 0; ni < 16; ni++) {
            const float2 s0 = __ldg(reinterpret_cast<const float2*>(simp + ni * 8 + l4 * 2));
            const float2 s1 = __ldg(reinterpret_cast<const float2*>(simp + 8 * N_ + ni * 8 + l4 * 2));
            s[ni][0] = fmaf(s[ni][0], c1, s0.x * c2);
            s[ni][1] = fmaf(s[ni][1], c1, s0.y * c2);
            s[ni][2] = fmaf(s[ni][2], c1, s1.x * c2);
            s[ni][3] = fmaf(s[ni][3], c1, s1.y * c2);
            zx0 = fmaxf(zx0, fmaxf(s[ni][0], s[ni][1]));
            zx1 = fmaxf(zx1, fmaxf(s[ni][2], s[ni][3]));
        }
        zx0 = fmaxf(zx0, __shfl_xor_sync(0xffffffffu, zx0, 1));
        zx0 = fmaxf(zx0, __shfl_xor_sync(0xffffffffu, zx0, 2));
        zx1 = fmaxf(zx1, __shfl_xor_sync(0xffffffffu, zx1, 1));
        zx1 = fmaxf(zx1, __shfl_xor_sync(0xffffffffu, zx1, 2));

        const float mn0 = fmaxf(m0, zx0), mn1 = fmaxf(m1, zx1);
        const float f0 = __expf(m0 - mn0), f1 = __expf(m1 - mn1);
        m0 = mn0; m1 = mn1;

        float ls0 = 0.f, ls1 = 0.f;
        uint32_t pa[8][4];
#pragma unroll
        for (int j = 0; j < 8; j++) {
            const float p00 = __expf(s[2 * j][0] - mn0);
            const float p01 = __expf(s[2 * j][1] - mn0);
            const float p02 = __expf(s[2 * j][2] - mn1);
            const float p03 = __expf(s[2 * j][3] - mn1);
            const float p10 = __expf(s[2 * j + 1][0] - mn0);
            const float p11 = __expf(s[2 * j + 1][1] - mn0);
            const float p12 = __expf(s[2 * j + 1][2] - mn1);
            const float p13 = __expf(s[2 * j + 1][3] - mn1);
            ls0 += p00 + p01 + p10 + p11;
            ls1 += p02 + p03 + p12 + p13;
            pa[j][0] = pack_bf2(p00, p01);
            pa[j][1] = pack_bf2(p02, p03);
            pa[j][2] = pack_bf2(p10, p11);
            pa[j][3] = pack_bf2(p12, p13);
        }
        ls0 += __shfl_xor_sync(0xffffffffu, ls0, 1);
        ls0 += __shfl_xor_sync(0xffffffffu, ls0, 2);
        ls1 += __shfl_xor_sync(0xffffffffu, ls1, 1);
        ls1 += __shfl_xor_sync(0xffffffffu, ls1, 2);
        l0 = l0 * f0 + ls0;
        l1 = l1 * f1 + ls1;

#pragma unroll
        for (int ni = 0; ni < 8; ni++) {
            o[ni][0] *= f0; o[ni][1] *= f0;
            o[ni][2] *= f1; o[ni][3] *= f1;
        }

#pragma unroll
        for (int j = 0; j < 8; j++) {
#pragma unroll
            for (int np = 0; np < 4; np++) {
                uint32_t bb[4];
                ldsm4t(bb, v_ln + j * 2304 + np * 32);
                mma_bf16(o[2 * np],     pa[j], bb);
                mma_bf16(o[2 * np + 1], pa[j], bb + 2);
            }
        }
    }

    const float inv0 = 1.f / l0, inv1 = 1.f / l1;
    __nv_bfloat16* op0 = att + (size_t)(b * N_ + qb + wm + l8) * D_ + h * HD_;
    __nv_bfloat16* op1 = op0 + 8 * D_;
#pragma unroll
    for (int ni = 0; ni < 8; ni++) {
        *reinterpret_cast<uint32_t*>(op0 + ni * 8 + l4 * 2)
            = pack_bf2(o[ni][0] * inv0, o[ni][1] * inv0);
        *reinterpret_cast<uint32_t*>(op1 + ni * 8 + l4 * 2)
            = pack_bf2(o[ni][2] * inv1, o[ni][3] * inv1);
    }
}

// ---------------------------------------------------------------------------
extern "C" void kernel_launch(void* const* d_in, const int* in_sizes, int n_in,
                              void* d_out, int out_size)
{
    const float* x      = (const float*)d_in[0];
    const float* gamma  = (const float*)d_in[1];
    const float* beta   = (const float*)d_in[2];
    const float* w_qkv  = (const float*)d_in[3];
    const float* w_proj = (const float*)d_in[4];
    const float* b_proj = (const float*)d_in[5];
    const float* swl    = (const float*)d_in[6];
    const float* sim    = (const float*)d_in[7];
    float* out = (float*)d_out;

    __nv_bfloat16 *xn, *qkvb, *attb, *wqb, *wpb;
    cudaGetSymbolAddress((void**)&xn,   g_xn);
    cudaGetSymbolAddress((void**)&qkvb, g_qkv);
    cudaGetSymbolAddress((void**)&attb, g_att);
    cudaGetSymbolAddress((void**)&wqb,  g_wqkv);
    cudaGetSymbolAddress((void**)&wpb,  g_wprj);

    // 0. Weight conversion fp32 -> bf16
    cvt_kernel<<<(D_ * 3 * D_ / 4 + 255) / 256, 256>>>(w_qkv, wqb, D_ * 3 * D_ / 4);
    cvt_kernel<<<(D_ * D_ / 4 + 255) / 256, 256>>>(w_proj, wpb, D_ * D_ / 4);

    // 1. LayerNorm (warp-per-row, fp32 in, bf16 out)
    ln_kernel<<<M_ / 8, 256>>>(x, gamma, beta, xn);

    // 2. QKV projection: bf16 GEMM (3-stage pipeline) -> bf16
    cudaFuncSetAttribute(bf16_gemm_kernel<3 * D_, false>,
                         cudaFuncAttributeMaxDynamicSharedMemorySize, GEMM_SMEM_BYTES);
    bf16_gemm_kernel<3 * D_, false><<<dim3(24, 32), 256, GEMM_SMEM_BYTES>>>(
        xn, wqb, qkvb, nullptr, nullptr);

    // 3. Attention (flash, bf16 mma, occ 2, register-resident P)
    cudaFuncSetAttribute(attn_bf16_kernel,
                         cudaFuncAttributeMaxDynamicSharedMemorySize, ATT_SMEM_BYTES);
    attn_bf16_kernel<<<dim3(8, 64), 256, ATT_SMEM_BYTES>>>(qkvb, sim, swl, attb);

    // 4. Output projection + bias + residual: bf16 GEMM (3-stage) -> fp32 d_out
    cudaFuncSetAttribute(bf16_gemm_kernel<D_, true>,
                         cudaFuncAttributeMaxDynamicSharedMemorySize, GEMM_SMEM_BYTES);
    bf16_gemm_kernel<D_, true><<<dim3(8, 32), 256, GEMM_SMEM_BYTES>>>(
        attb, wpb, out, b_proj, x);
}